// round 1
// baseline (speedup 1.0000x reference)
#include <cuda_runtime.h>
#include <cuda_bf16.h>

// Problem constants
#define Hdim 512
#define Wdim 512
#define PH 16
#define PW 16
#define Qn 3
#define NHp 32
#define NWp 32
#define Pn 1024
#define Bn 64
#define JITTER 1e-6f

#define NT 16           // tiles (batch items) per block
#define TSTRIDE 17      // padded row stride (in float2) for transpose buffer

// ---------------------------------------------------------------------------
// Fully unrolled 16-point complex FFT (DIT, input bit-reversal, natural output)
// DIR = -1 : forward (e^{-i2pi jk/N});  DIR = +1 : inverse (unnormalized)
// ---------------------------------------------------------------------------
template<int DIR>
__device__ __forceinline__ void fft16(float re[16], float im[16]) {
    // bit reversal for N=16
#define SWAPF(a,b) { float _t=re[a]; re[a]=re[b]; re[b]=_t; _t=im[a]; im[a]=im[b]; im[b]=_t; }
    SWAPF(1, 8) SWAPF(2, 4) SWAPF(3, 12) SWAPF(5, 10) SWAPF(7, 14) SWAPF(11, 13)
#undef SWAPF

    // twiddle tables for theta = pi*j/8, j = 0..7
    const float CT[8] = { 1.0f,  0.9238795325112867f,  0.7071067811865476f,  0.3826834323650898f,
                          0.0f, -0.3826834323650898f, -0.7071067811865476f, -0.9238795325112867f };
    const float ST[8] = { 0.0f,  0.3826834323650898f,  0.7071067811865476f,  0.9238795325112867f,
                          1.0f,  0.9238795325112867f,  0.7071067811865476f,  0.3826834323650898f };

#pragma unroll
    for (int s = 1; s <= 4; ++s) {
        const int len   = 1 << s;
        const int half  = len >> 1;
        const int tstep = 16 >> s;
#pragma unroll
        for (int i = 0; i < 16; i += len) {
#pragma unroll
            for (int j = 0; j < half; ++j) {
                const float c  = CT[j * tstep];
                const float sn = (float)DIR * ST[j * tstep];
                const int a = i + j;
                const int b = a + half;
                float br = re[b], bi = im[b];
                float tr = c * br - sn * bi;
                float ti = c * bi + sn * br;
                re[b] = re[a] - tr;
                im[b] = im[a] - ti;
                re[a] += tr;
                im[a] += ti;
            }
        }
    }
}

// ---------------------------------------------------------------------------
// Fused kernel: per block = (one patch p, 16 batch tiles).
//   stage 0: 256 threads compute S[p]/256 into smem (one freq bin each) + bias
//   stage 1: per tile (16 threads, one row each):
//            row FFT -> smem transpose -> col FFT -> *S -> inv col FFT
//            -> smem transpose -> inv row FFT -> +bias -> store
// ---------------------------------------------------------------------------
__global__ __launch_bounds__(256) void patch_spectral_kernel(
    const float* __restrict__ x,
    const float* __restrict__ logits,
    const float* __restrict__ mu,
    const float* __restrict__ sigma,
    const float* __restrict__ bias,
    float* __restrict__ y)
{
    __shared__ float2 sbuf[NT][16 * TSTRIDE];   // per-tile transpose buffers
    __shared__ float  sS[256];                  // S[p][ky][kx] / 256
    __shared__ float  sBt[256];                 // bias transposed: sBt[j*16+i]

    const int p  = blockIdx.x >> 2;   // patch index
    const int bg = blockIdx.x & 3;    // batch group (16 tiles each)
    const int t  = threadIdx.x;

    // ---- stage 0: spectrum S (exact softmax + Gaussian mixture), bias ----
    {
        const int ky = t >> 4;
        const int kx = t & 15;
        const float fy = (float)(ky < 8 ? ky : ky - 16) * (1.0f / 16.0f);
        const float fx = (float)(kx < 8 ? kx : kx - 16) * (1.0f / 16.0f);

        const float l0 = logits[p * Qn + 0];
        const float l1 = logits[p * Qn + 1];
        const float l2 = logits[p * Qn + 2];
        const float mx = fmaxf(l0, fmaxf(l1, l2));
        const float e0 = expf(l0 - mx);
        const float e1 = expf(l1 - mx);
        const float e2 = expf(l2 - mx);
        const float inv = 1.0f / (e0 + e1 + e2);
        const float wq[3] = { e0 * inv, e1 * inv, e2 * inv };

        float acc = 0.0f;
#pragma unroll
        for (int q = 0; q < Qn; ++q) {
            const int base = (p * Qn + q) * 2;
            const float muy = mu[base + 0];
            const float mux = mu[base + 1];
            const float isy = 1.0f / sigma[base + 0];
            const float isx = 1.0f / sigma[base + 1];
            const float a1 = (fy - muy) * isy, b1 = (fx - mux) * isx;
            const float a2 = (fy + muy) * isy, b2 = (fx + mux) * isx;
            const float g1 = expf(-0.5f * (a1 * a1 + b1 * b1));
            const float g2 = expf(-0.5f * (a2 * a2 + b2 * b2));
            acc += wq[q] * (g1 + g2);
        }
        sS[t] = (acc + JITTER) * (1.0f / 256.0f);

        // bias stored transposed for conflict-free reads in stage 3
        const int bi = t >> 4;   // row i
        const int bj = t & 15;   // col j
        sBt[bj * 16 + bi] = bias[p * 256 + t];
    }
    __syncthreads();

    // ---- stage 1..3: FFT pipeline ----
    const int tile = t >> 4;          // 0..15 within block
    const int r    = t & 15;          // row owned by this thread
    const int b    = bg * NT + tile;  // batch index
    const int py   = p >> 5;          // p / NW
    const int px   = p & 31;          // p % NW

    const size_t row_off = ((size_t)b * Hdim + (size_t)py * PH + r) * Wdim + (size_t)px * PW;
    const float* xrow = x + row_off;

    float re[16], im[16];
    {
        float4 v0 = *(const float4*)(xrow + 0);
        float4 v1 = *(const float4*)(xrow + 4);
        float4 v2 = *(const float4*)(xrow + 8);
        float4 v3 = *(const float4*)(xrow + 12);
        re[0]=v0.x; re[1]=v0.y; re[2]=v0.z; re[3]=v0.w;
        re[4]=v1.x; re[5]=v1.y; re[6]=v1.z; re[7]=v1.w;
        re[8]=v2.x; re[9]=v2.y; re[10]=v2.z; re[11]=v2.w;
        re[12]=v3.x; re[13]=v3.y; re[14]=v3.z; re[15]=v3.w;
    }
#pragma unroll
    for (int j = 0; j < 16; ++j) im[j] = 0.0f;

    // forward row FFT: X1[i=r, kx=0..15]
    fft16<-1>(re, im);

    float2* buf = sbuf[tile];
#pragma unroll
    for (int n = 0; n < 16; ++n) buf[n * TSTRIDE + r] = make_float2(re[n], im[n]);
    __syncwarp();

    // read column kx=r: X1[i=0..15, kx=r]
#pragma unroll
    for (int n = 0; n < 16; ++n) { float2 v = buf[r * TSTRIDE + n]; re[n] = v.x; im[n] = v.y; }

    // forward column FFT -> X2[ky, kx=r]
    fft16<-1>(re, im);

    // multiply by S/256 (real)
#pragma unroll
    for (int k = 0; k < 16; ++k) {
        const float sv = sS[k * 16 + r];
        re[k] *= sv;
        im[k] *= sv;
    }

    // inverse column FFT -> W[i, kx=r]
    fft16<1>(re, im);

    __syncwarp();   // all lanes of this tile done reading buf
#pragma unroll
    for (int n = 0; n < 16; ++n) buf[n * TSTRIDE + r] = make_float2(re[n], im[n]);
    __syncwarp();

    // read row i=r: W[i=r, kx=0..15]
#pragma unroll
    for (int n = 0; n < 16; ++n) { float2 v = buf[r * TSTRIDE + n]; re[n] = v.x; im[n] = v.y; }

    // inverse row FFT -> y[i=r, j] (real part), add bias, store
    fft16<1>(re, im);

    float* yrow = y + row_off;
#pragma unroll
    for (int j = 0; j < 16; j += 4) {
        float4 o;
        o.x = re[j + 0] + sBt[(j + 0) * 16 + r];
        o.y = re[j + 1] + sBt[(j + 1) * 16 + r];
        o.z = re[j + 2] + sBt[(j + 2) * 16 + r];
        o.w = re[j + 3] + sBt[(j + 3) * 16 + r];
        *(float4*)(yrow + j) = o;
    }
}

extern "C" void kernel_launch(void* const* d_in, const int* in_sizes, int n_in,
                              void* d_out, int out_size)
{
    const float* x      = (const float*)d_in[0];
    const float* logits = (const float*)d_in[1];
    const float* mu     = (const float*)d_in[2];
    const float* sigma  = (const float*)d_in[3];
    const float* bias   = (const float*)d_in[4];
    float* y = (float*)d_out;

    // grid: P patches * (B / NT) batch groups
    dim3 grid(Pn * (Bn / NT));
    dim3 block(256);
    patch_spectral_kernel<<<grid, block>>>(x, logits, mu, sigma, bias, y);
}

// round 2
// speedup vs baseline: 1.0215x; 1.0215x over previous
#include <cuda_runtime.h>
#include <cuda_bf16.h>

// Problem constants
#define Hdim 512
#define Wdim 512
#define PH 16
#define PW 16
#define Qn 3
#define NHp 32
#define NWp 32
#define Pn 1024
#define Bn 64
#define JITTER 1e-6f

#define NT 16           // tiles per block (2 patches x 8 batches)
#define TSTRIDE 17      // padded row stride (in float2) for transpose buffer

// Precomputed spectrum scratch: S[p][ky*16+kx] / 256
__device__ float g_S[Pn * 256];

// ---------------------------------------------------------------------------
// Kernel A: build S once per patch, exploiting separability of the Gaussians.
// block = one patch, 256 threads (one per frequency bin).
// ---------------------------------------------------------------------------
__global__ __launch_bounds__(256) void make_S_kernel(
    const float* __restrict__ logits,
    const float* __restrict__ mu,
    const float* __restrict__ sigma)
{
    __shared__ float w[4];
    __shared__ float gy[6][16];   // [q*2+sign][ky]
    __shared__ float gx[6][16];   // [q*2+sign][kx]

    const int p = blockIdx.x;
    const int t = threadIdx.x;

    if (t == 0) {
        const float l0 = logits[p * Qn + 0];
        const float l1 = logits[p * Qn + 1];
        const float l2 = logits[p * Qn + 2];
        const float mx = fmaxf(l0, fmaxf(l1, l2));
        const float e0 = expf(l0 - mx);
        const float e1 = expf(l1 - mx);
        const float e2 = expf(l2 - mx);
        const float inv = 1.0f / (e0 + e1 + e2);
        w[0] = e0 * inv; w[1] = e1 * inv; w[2] = e2 * inv;
    }
    if (t < 192) {
        // t -> axis (0=y,1=x), qs = q*2+sign, k
        const int axis = t / 96;
        const int rem  = t % 96;
        const int qs   = rem >> 4;
        const int k    = rem & 15;
        const int q    = qs >> 1;
        const int sgn  = qs & 1;          // 0: (f - mu), 1: (f + mu)
        const float f  = (float)(k < 8 ? k : k - 16) * (1.0f / 16.0f);
        const int base = (p * Qn + q) * 2;
        const float m  = mu[base + axis];     // axis 0 -> mu_y, 1 -> mu_x
        const float s  = sigma[base + axis];
        const float d  = (sgn ? (f + m) : (f - m)) / s;
        const float v  = expf(-0.5f * d * d);
        if (axis == 0) gy[qs][k] = v; else gx[qs][k] = v;
    }
    __syncthreads();

    const int ky = t >> 4;
    const int kx = t & 15;
    float acc = 0.0f;
#pragma unroll
    for (int q = 0; q < Qn; ++q) {
        acc += w[q] * (gy[2 * q][ky] * gx[2 * q][kx] +
                       gy[2 * q + 1][ky] * gx[2 * q + 1][kx]);
    }
    g_S[p * 256 + t] = (acc + JITTER) * (1.0f / 256.0f);
}

// ---------------------------------------------------------------------------
// Fully unrolled 16-point complex FFT (DIT, input bit-reversal, natural output)
// DIR = -1 : forward;  DIR = +1 : inverse (unnormalized)
// ---------------------------------------------------------------------------
template<int DIR>
__device__ __forceinline__ void fft16(float re[16], float im[16]) {
#define SWAPF(a,b) { float _t=re[a]; re[a]=re[b]; re[b]=_t; _t=im[a]; im[a]=im[b]; im[b]=_t; }
    SWAPF(1, 8) SWAPF(2, 4) SWAPF(3, 12) SWAPF(5, 10) SWAPF(7, 14) SWAPF(11, 13)
#undef SWAPF

    const float CT[8] = { 1.0f,  0.9238795325112867f,  0.7071067811865476f,  0.3826834323650898f,
                          0.0f, -0.3826834323650898f, -0.7071067811865476f, -0.9238795325112867f };
    const float ST[8] = { 0.0f,  0.3826834323650898f,  0.7071067811865476f,  0.9238795325112867f,
                          1.0f,  0.9238795325112867f,  0.7071067811865476f,  0.3826834323650898f };

#pragma unroll
    for (int s = 1; s <= 4; ++s) {
        const int len   = 1 << s;
        const int half  = len >> 1;
        const int tstep = 16 >> s;
#pragma unroll
        for (int i = 0; i < 16; i += len) {
#pragma unroll
            for (int j = 0; j < half; ++j) {
                const float c  = CT[j * tstep];
                const float sn = (float)DIR * ST[j * tstep];
                const int a = i + j;
                const int b = a + half;
                float br = re[b], bi = im[b];
                float tr = c * br - sn * bi;
                float ti = c * bi + sn * br;
                re[b] = re[a] - tr;
                im[b] = im[a] - ti;
                re[a] += tr;
                im[a] += ti;
            }
        }
    }
}

// ---------------------------------------------------------------------------
// Kernel B: per block = (one patch PAIR, 8 batch items) = 16 tiles.
// Warp = 2 tiles = (patch 2pp | 2pp+1) x same batch -> lane r and lane 16+r
// touch the two 64B halves of the same 128B gmem line (full sectors).
// ---------------------------------------------------------------------------
__global__ __launch_bounds__(256) void patch_spectral_kernel(
    const float* __restrict__ x,
    const float* __restrict__ bias,
    float* __restrict__ y)
{
    __shared__ float2 sbuf[NT][16 * TSTRIDE];   // per-tile transpose buffers
    __shared__ float  sS[2][272];               // S/256 per patch (pad 272 to split banks)
    __shared__ float  sBt[2][272];              // bias transposed: sBt[h][j*16+i]

    const int pp = blockIdx.x & 511;            // patch-pair index (0..511)
    const int bg = blockIdx.x >> 9;             // batch group (0..7)
    const int t  = threadIdx.x;

    const int p0 = pp * 2;
    // ---- stage 0: stage S and bias for the two patches ----
    {
#pragma unroll
        for (int hh = 0; hh < 2; ++hh) {
            sS[hh][t] = g_S[(p0 + hh) * 256 + t];
            const float bv = bias[(p0 + hh) * 256 + t];
            const int bi = t >> 4;   // row i
            const int bj = t & 15;   // col j
            sBt[hh][bj * 16 + bi] = bv;   // transposed for conflict-free epilogue
        }
    }
    __syncthreads();

    // ---- FFT pipeline ----
    const int tile = t >> 4;          // 0..15
    const int half = tile & 1;        // which patch of the pair
    const int warp = t >> 5;          // 0..7 -> batch within group
    const int r    = t & 15;          // row owned by this thread
    const int b    = bg * 8 + warp;   // batch index
    const int p    = p0 + half;
    const int py   = p >> 5;
    const int px   = p & 31;

    const size_t row_off = ((size_t)b * Hdim + (size_t)py * PH + r) * Wdim + (size_t)px * PW;
    const float* xrow = x + row_off;

    float re[16], im[16];
    {
        float4 v0 = *(const float4*)(xrow + 0);
        float4 v1 = *(const float4*)(xrow + 4);
        float4 v2 = *(const float4*)(xrow + 8);
        float4 v3 = *(const float4*)(xrow + 12);
        re[0]=v0.x; re[1]=v0.y; re[2]=v0.z; re[3]=v0.w;
        re[4]=v1.x; re[5]=v1.y; re[6]=v1.z; re[7]=v1.w;
        re[8]=v2.x; re[9]=v2.y; re[10]=v2.z; re[11]=v2.w;
        re[12]=v3.x; re[13]=v3.y; re[14]=v3.z; re[15]=v3.w;
    }
#pragma unroll
    for (int j = 0; j < 16; ++j) im[j] = 0.0f;

    // forward row FFT
    fft16<-1>(re, im);

    float2* buf = sbuf[tile];
#pragma unroll
    for (int n = 0; n < 16; ++n) buf[n * TSTRIDE + r] = make_float2(re[n], im[n]);
    __syncwarp();

#pragma unroll
    for (int n = 0; n < 16; ++n) { float2 v = buf[r * TSTRIDE + n]; re[n] = v.x; im[n] = v.y; }

    // forward column FFT
    fft16<-1>(re, im);

    // multiply by S/256 (real, even spectrum)
    const float* sSh = sS[half];
#pragma unroll
    for (int k = 0; k < 16; ++k) {
        const float sv = sSh[k * 16 + r];
        re[k] *= sv;
        im[k] *= sv;
    }

    // inverse column FFT
    fft16<1>(re, im);

    __syncwarp();
#pragma unroll
    for (int n = 0; n < 16; ++n) buf[n * TSTRIDE + r] = make_float2(re[n], im[n]);
    __syncwarp();

#pragma unroll
    for (int n = 0; n < 16; ++n) { float2 v = buf[r * TSTRIDE + n]; re[n] = v.x; im[n] = v.y; }

    // inverse row FFT -> real output + bias
    fft16<1>(re, im);

    const float* sBh = sBt[half];
    float* yrow = y + row_off;
#pragma unroll
    for (int j = 0; j < 16; j += 4) {
        float4 o;
        o.x = re[j + 0] + sBh[(j + 0) * 16 + r];
        o.y = re[j + 1] + sBh[(j + 1) * 16 + r];
        o.z = re[j + 2] + sBh[(j + 2) * 16 + r];
        o.w = re[j + 3] + sBh[(j + 3) * 16 + r];
        *(float4*)(yrow + j) = o;
    }
}

extern "C" void kernel_launch(void* const* d_in, const int* in_sizes, int n_in,
                              void* d_out, int out_size)
{
    const float* x      = (const float*)d_in[0];
    const float* logits = (const float*)d_in[1];
    const float* mu     = (const float*)d_in[2];
    const float* sigma  = (const float*)d_in[3];
    const float* bias   = (const float*)d_in[4];
    float* y = (float*)d_out;

    make_S_kernel<<<Pn, 256>>>(logits, mu, sigma);
    patch_spectral_kernel<<<(Pn / 2) * (Bn / 8), 256>>>(x, bias, y);
}

// round 4
// speedup vs baseline: 1.5951x; 1.5615x over previous
#include <cuda_runtime.h>
#include <cuda_bf16.h>

#define Hdim 512
#define Wdim 512
#define Qn 3
#define Pn 1024
#define Bn 64
#define JITTER 1e-6f

// Precomputed symmetrized spectrum: S_sym[p][ky*16+kx] / 256
__device__ float g_S[Pn * 256];

// ---------------------------------------------------------------------------
// Kernel A: build S per patch (separable Gaussians), then index-symmetrize:
//   S_sym[k] = (S[k] + S[(-k) mod 16]) / 2
// This makes Xf*S_sym exactly Hermitian, matching the reference's .real
// (Re(ifft(Xf*S)) == ifft(Xf*S_sym) for Hermitian Xf, real S).
// ---------------------------------------------------------------------------
__global__ __launch_bounds__(256) void make_S_kernel(
    const float* __restrict__ logits,
    const float* __restrict__ mu,
    const float* __restrict__ sigma)
{
    __shared__ float w[4];
    __shared__ float gy[6][16];
    __shared__ float gx[6][16];
    __shared__ float sAcc[256];

    const int p = blockIdx.x;
    const int t = threadIdx.x;

    if (t == 0) {
        const float l0 = logits[p * Qn + 0];
        const float l1 = logits[p * Qn + 1];
        const float l2 = logits[p * Qn + 2];
        const float mx = fmaxf(l0, fmaxf(l1, l2));
        const float e0 = expf(l0 - mx);
        const float e1 = expf(l1 - mx);
        const float e2 = expf(l2 - mx);
        const float inv = 1.0f / (e0 + e1 + e2);
        w[0] = e0 * inv; w[1] = e1 * inv; w[2] = e2 * inv;
    }
    if (t < 192) {
        const int axis = t / 96;
        const int rem  = t % 96;
        const int qs   = rem >> 4;
        const int k    = rem & 15;
        const int q    = qs >> 1;
        const int sgn  = qs & 1;
        const float f  = (float)(k < 8 ? k : k - 16) * (1.0f / 16.0f);
        const int base = (p * Qn + q) * 2;
        const float m  = mu[base + axis];
        const float s  = sigma[base + axis];
        const float d  = (sgn ? (f + m) : (f - m)) / s;
        const float v  = expf(-0.5f * d * d);
        if (axis == 0) gy[qs][k] = v; else gx[qs][k] = v;
    }
    __syncthreads();

    const int ky = t >> 4;
    const int kx = t & 15;
    float acc = 0.0f;
#pragma unroll
    for (int q = 0; q < Qn; ++q) {
        acc += w[q] * (gy[2 * q][ky] * gx[2 * q][kx] +
                       gy[2 * q + 1][ky] * gx[2 * q + 1][kx]);
    }
    sAcc[t] = acc;
    __syncthreads();

    const int tm = (((16 - ky) & 15) << 4) | ((16 - kx) & 15);
    const float ssym = 0.5f * (sAcc[t] + sAcc[tm]) + JITTER;
    g_S[p * 256 + t] = ssym * (1.0f / 256.0f);
}

// ---------------------------------------------------------------------------
// Fully unrolled 16-point complex FFT. DIR=-1 fwd, DIR=+1 inv (unnormalized).
// ---------------------------------------------------------------------------
template<int DIR>
__device__ __forceinline__ void fft16(float re[16], float im[16]) {
#define SWAPF(a,b) { float _t=re[a]; re[a]=re[b]; re[b]=_t; _t=im[a]; im[a]=im[b]; im[b]=_t; }
    SWAPF(1, 8) SWAPF(2, 4) SWAPF(3, 12) SWAPF(5, 10) SWAPF(7, 14) SWAPF(11, 13)
#undef SWAPF
    const float CT[8] = { 1.0f,  0.9238795325112867f,  0.7071067811865476f,  0.3826834323650898f,
                          0.0f, -0.3826834323650898f, -0.7071067811865476f, -0.9238795325112867f };
    const float ST[8] = { 0.0f,  0.3826834323650898f,  0.7071067811865476f,  0.9238795325112867f,
                          1.0f,  0.9238795325112867f,  0.7071067811865476f,  0.3826834323650898f };
#pragma unroll
    for (int s = 1; s <= 4; ++s) {
        const int len   = 1 << s;
        const int half  = len >> 1;
        const int tstep = 16 >> s;
#pragma unroll
        for (int i = 0; i < 16; i += len) {
#pragma unroll
            for (int j = 0; j < half; ++j) {
                const float c  = CT[j * tstep];
                const float sn = (float)DIR * ST[j * tstep];
                const int a = i + j;
                const int b = a + half;
                float br = re[b], bi = im[b];
                float tr = c * br - sn * bi;
                float ti = c * bi + sn * br;
                re[b] = re[a] - tr;
                im[b] = im[a] - ti;
                re[a] += tr;
                im[a] += ti;
            }
        }
    }
}

// ---------------------------------------------------------------------------
// Kernel B: block = one adjacent patch pair (A,B) x 16 batches.
// Group of 16 lanes handles both tiles of the pair for one batch:
//   phase 1: lane r packs row r of A + i*row r of B -> 1 fft16 (2 real rows),
//            Hermitian unpack kx=0..8, store 16 strips (col 0&8 packed real)
//   phase 2: lane = (tile, col task): fwd fft16, x S_sym, inv fft16
//   phase 3: lane i: Hermitian-extend W rows, pack A+iB, 1 ifft16
//            -> y_A = Re, y_B = Im, +bias, contiguous 128B stores
// ---------------------------------------------------------------------------
__global__ __launch_bounds__(256, 4) void patch_spectral_kernel(
    const float* __restrict__ x,
    const float* __restrict__ bias,
    float* __restrict__ y)
{
    __shared__ float2 colbuf[16][272];   // per group: 16 strips of 17 float2
    __shared__ float  sS[2][272];        // S_sym/256 per patch of the pair
    __shared__ float  sBt[2][272];       // bias transposed: sBt[h][j*16+i]

    const int pp = blockIdx.x & 511;     // patch-pair index
    const int bg = blockIdx.x >> 9;      // batch group (16 batches)
    const int t  = threadIdx.x;
    const int p0 = pp * 2;

#pragma unroll
    for (int hh = 0; hh < 2; ++hh) {
        sS[hh][t] = g_S[(p0 + hh) * 256 + t];
        sBt[hh][(t & 15) * 16 + (t >> 4)] = bias[(p0 + hh) * 256 + t];
    }
    __syncthreads();

    const int g  = t >> 4;        // group = batch within group-of-16
    const int ln = t & 15;        // lane in group
    const int b  = bg * 16 + g;
    const int py = p0 >> 5;
    const int px0 = p0 & 31;

    float2* buf = colbuf[g];
    const size_t base = ((size_t)b * Hdim + (size_t)(py * 16 + ln)) * Wdim + (size_t)px0 * 16;

    float zr[16], zi[16];

    // ---- phase 1: load rows (A,B contiguous 128B), packed row FFT ----
    {
        const float* xr = x + base;
#pragma unroll
        for (int q = 0; q < 4; ++q) {
            float4 va = *(const float4*)(xr + q * 4);
            float4 vb = *(const float4*)(xr + 16 + q * 4);
            zr[q*4+0]=va.x; zr[q*4+1]=va.y; zr[q*4+2]=va.z; zr[q*4+3]=va.w;
            zi[q*4+0]=vb.x; zi[q*4+1]=vb.y; zi[q*4+2]=vb.z; zi[q*4+3]=vb.w;
        }
    }
    fft16<-1>(zr, zi);

    // Hermitian unpack, store column strips
    buf[0 * 17 + ln]         = make_float2(zr[0], zr[8]);   // A: (X[r,0], X[r,8]) real pair
    buf[(8 + 0) * 17 + ln]   = make_float2(zi[0], zi[8]);   // B
#pragma unroll
    for (int k = 1; k <= 7; ++k) {
        const int m = 16 - k;
        buf[k * 17 + ln]       = make_float2(0.5f * (zr[k] + zr[m]), 0.5f * (zi[k] - zi[m]));
        buf[(8 + k) * 17 + ln] = make_float2(0.5f * (zi[k] + zi[m]), 0.5f * (zr[m] - zr[k]));
    }
    __syncwarp();

    // ---- phase 2: column task (tile = ln>>3, tt = ln&7) ----
    {
        const int tile = ln >> 3;
        const int tt   = ln & 7;
        float2* strip = buf + ln * 17;
#pragma unroll
        for (int r = 0; r < 16; ++r) { float2 v = strip[r]; zr[r] = v.x; zi[r] = v.y; }

        fft16<-1>(zr, zi);

        const float* Sp = sS[tile];
        if (tt == 0) {
            // packed real cols 0 & 8 (S_sym even in ky at kx=0,8)
#pragma unroll
            for (int ky = 0; ky <= 8; ++ky) {
                const int m = (16 - ky) & 15;
                const float s0 = Sp[ky * 16 + 0];
                const float s8 = Sp[ky * 16 + 8];
                const float c0r = 0.5f * (zr[ky] + zr[m]);
                const float c0i = 0.5f * (zi[ky] - zi[m]);
                const float c8r = 0.5f * (zi[ky] + zi[m]);
                const float c8i = 0.5f * (zr[m] - zr[ky]);
                const float ar = c0r * s0, ai = c0i * s0;
                const float br = c8r * s8, bi = c8i * s8;
                zr[ky] = ar - bi;  zi[ky] = ai + br;
                if (m != ky) { zr[m] = ar + bi; zi[m] = br - ai; }
            }
        } else {
#pragma unroll
            for (int ky = 0; ky < 16; ++ky) {
                const float s = Sp[ky * 16 + tt];
                zr[ky] *= s;  zi[ky] *= s;
            }
        }

        fft16<1>(zr, zi);

#pragma unroll
        for (int i = 0; i < 16; ++i) strip[i] = make_float2(zr[i], zi[i]);
    }
    __syncwarp();

    // ---- phase 3: Hermitian-extend W rows, packed inverse row FFT ----
    {
        float2 a0 = buf[0 * 17 + ln];
        float2 b0 = buf[(8 + 0) * 17 + ln];
        zr[0] = a0.x;  zi[0] = b0.x;
        zr[8] = a0.y;  zi[8] = b0.y;
#pragma unroll
        for (int k = 1; k <= 7; ++k) {
            float2 a = buf[k * 17 + ln];        // W_A[i,k]
            float2 c = buf[(8 + k) * 17 + ln];  // W_B[i,k]
            zr[k]      = a.x - c.y;   zi[k]      = a.y + c.x;   // W_A + i W_B
            zr[16 - k] = a.x + c.y;   zi[16 - k] = c.x - a.y;   // conj ext
        }
    }
    fft16<1>(zr, zi);

    // ---- epilogue: +bias, store two contiguous rows (128B) ----
    {
        const float* bA = sBt[0];
        const float* bB = sBt[1];
        float* yr = y + base;
#pragma unroll
        for (int j = 0; j < 16; j += 4) {
            float4 oa, ob;
            oa.x = zr[j+0] + bA[(j+0)*16 + ln];
            oa.y = zr[j+1] + bA[(j+1)*16 + ln];
            oa.z = zr[j+2] + bA[(j+2)*16 + ln];
            oa.w = zr[j+3] + bA[(j+3)*16 + ln];
            ob.x = zi[j+0] + bB[(j+0)*16 + ln];
            ob.y = zi[j+1] + bB[(j+1)*16 + ln];
            ob.z = zi[j+2] + bB[(j+2)*16 + ln];
            ob.w = zi[j+3] + bB[(j+3)*16 + ln];
            *(float4*)(yr + j)      = oa;
            *(float4*)(yr + 16 + j) = ob;
        }
    }
}

extern "C" void kernel_launch(void* const* d_in, const int* in_sizes, int n_in,
                              void* d_out, int out_size)
{
    const float* x      = (const float*)d_in[0];
    const float* logits = (const float*)d_in[1];
    const float* mu     = (const float*)d_in[2];
    const float* sigma  = (const float*)d_in[3];
    const float* bias   = (const float*)d_in[4];
    float* y = (float*)d_out;

    make_S_kernel<<<Pn, 256>>>(logits, mu, sigma);
    patch_spectral_kernel<<<2048, 256>>>(x, bias, y);
}

// round 5
// speedup vs baseline: 1.7944x; 1.1249x over previous
#include <cuda_runtime.h>
#include <cuda_bf16.h>

#define Hdim 512
#define Wdim 512
#define Qn 3
#define Pn 1024
#define Bn 64
#define JITTER 1e-6f

// Precomputed symmetrized spectrum: S_sym[p][ky*16+kx] / 256
__device__ float g_S[Pn * 256];

// ---------------------------------------------------------------------------
// Kernel A: build S per patch (separable Gaussians), then index-symmetrize:
//   S_sym[k] = (S[k] + S[(-k) mod 16]) / 2    (makes Xf*S exactly Hermitian)
// ---------------------------------------------------------------------------
__global__ __launch_bounds__(256) void make_S_kernel(
    const float* __restrict__ logits,
    const float* __restrict__ mu,
    const float* __restrict__ sigma)
{
    __shared__ float w[4];
    __shared__ float gy[6][16];
    __shared__ float gx[6][16];
    __shared__ float sAcc[256];

    const int p = blockIdx.x;
    const int t = threadIdx.x;

    if (t == 0) {
        const float l0 = logits[p * Qn + 0];
        const float l1 = logits[p * Qn + 1];
        const float l2 = logits[p * Qn + 2];
        const float mx = fmaxf(l0, fmaxf(l1, l2));
        const float e0 = expf(l0 - mx);
        const float e1 = expf(l1 - mx);
        const float e2 = expf(l2 - mx);
        const float inv = 1.0f / (e0 + e1 + e2);
        w[0] = e0 * inv; w[1] = e1 * inv; w[2] = e2 * inv;
    }
    if (t < 192) {
        const int axis = t / 96;
        const int rem  = t % 96;
        const int qs   = rem >> 4;
        const int k    = rem & 15;
        const int q    = qs >> 1;
        const int sgn  = qs & 1;
        const float f  = (float)(k < 8 ? k : k - 16) * (1.0f / 16.0f);
        const int base = (p * Qn + q) * 2;
        const float m  = mu[base + axis];
        const float s  = sigma[base + axis];
        const float d  = (sgn ? (f + m) : (f - m)) / s;
        const float v  = expf(-0.5f * d * d);
        if (axis == 0) gy[qs][k] = v; else gx[qs][k] = v;
    }
    __syncthreads();

    const int ky = t >> 4;
    const int kx = t & 15;
    float acc = 0.0f;
#pragma unroll
    for (int q = 0; q < Qn; ++q) {
        acc += w[q] * (gy[2 * q][ky] * gx[2 * q][kx] +
                       gy[2 * q + 1][ky] * gx[2 * q + 1][kx]);
    }
    sAcc[t] = acc;
    __syncthreads();

    const int tm = (((16 - ky) & 15) << 4) | ((16 - kx) & 15);
    const float ssym = 0.5f * (sAcc[t] + sAcc[tm]) + JITTER;
    g_S[p * 256 + t] = ssym * (1.0f / 256.0f);
}

// ---------------------------------------------------------------------------
// Fully unrolled 16-point complex FFT. DIR=-1 fwd, DIR=+1 inv (unnormalized).
// ---------------------------------------------------------------------------
template<int DIR>
__device__ __forceinline__ void fft16(float re[16], float im[16]) {
#define SWAPF(a,b) { float _t=re[a]; re[a]=re[b]; re[b]=_t; _t=im[a]; im[a]=im[b]; im[b]=_t; }
    SWAPF(1, 8) SWAPF(2, 4) SWAPF(3, 12) SWAPF(5, 10) SWAPF(7, 14) SWAPF(11, 13)
#undef SWAPF
    const float CT[8] = { 1.0f,  0.9238795325112867f,  0.7071067811865476f,  0.3826834323650898f,
                          0.0f, -0.3826834323650898f, -0.7071067811865476f, -0.9238795325112867f };
    const float ST[8] = { 0.0f,  0.3826834323650898f,  0.7071067811865476f,  0.9238795325112867f,
                          1.0f,  0.9238795325112867f,  0.7071067811865476f,  0.3826834323650898f };
#pragma unroll
    for (int s = 1; s <= 4; ++s) {
        const int len   = 1 << s;
        const int half  = len >> 1;
        const int tstep = 16 >> s;
#pragma unroll
        for (int i = 0; i < 16; i += len) {
#pragma unroll
            for (int j = 0; j < half; ++j) {
                const float c  = CT[j * tstep];
                const float sn = (float)DIR * ST[j * tstep];
                const int a = i + j;
                const int b = a + half;
                float br = re[b], bi = im[b];
                float tr = c * br - sn * bi;
                float ti = c * bi + sn * br;
                re[b] = re[a] - tr;
                im[b] = im[a] - ti;
                re[a] += tr;
                im[a] += ti;
            }
        }
    }
}

// ---------------------------------------------------------------------------
// Kernel B: block = one adjacent patch pair (A,B) x 16 batches.
// Global I/O is staged through smem so every LDG/STG.128 covers 4 full
// 128B segments (100% sector use). Per-group stage region = 576 floats,
// row r at float offset g*576 + r*36 (36-stride -> conflict-free phases).
// ---------------------------------------------------------------------------
__global__ __launch_bounds__(256, 4) void patch_spectral_kernel(
    const float* __restrict__ x,
    const float* __restrict__ bias,
    float* __restrict__ y)
{
    __shared__ float2 colbuf[16][288];   // per group: stage (576 f) / strips (272 f2)
    __shared__ float  sS[2][272];        // S_sym/256 per patch of the pair
    __shared__ float  sBt[2][272];       // bias transposed: sBt[h][j*16+i]

    const int pp = blockIdx.x & 511;     // patch-pair index
    const int bg = blockIdx.x >> 9;      // batch group (16 batches)
    const int t  = threadIdx.x;
    const int p0 = pp * 2;

#pragma unroll
    for (int hh = 0; hh < 2; ++hh) {
        sS[hh][t] = g_S[(p0 + hh) * 256 + t];
        sBt[hh][(t & 15) * 16 + (t >> 4)] = bias[(p0 + hh) * 256 + t];
    }
    __syncthreads();

    const int wrp = t >> 5;       // warp 0..7
    const int l   = t & 31;       // lane
    const int g0  = wrp * 2;      // two groups (batches) per warp
    const int py  = p0 >> 5;
    const int px0 = p0 & 31;

    float* ss = (float*)colbuf;   // flat stage view

    // ---- staged coalesced load: 8 x LDG.128, each instr = 4 full segments --
    {
        const int seg = l >> 3;          // which of 4 segments this lane serves
        const int c4  = (l & 7) * 4;     // float offset within 128B segment
#pragma unroll
        for (int i = 0; i < 8; ++i) {
            const int q   = i * 4 + seg;        // 0..31
            const int gof = q >> 4;
            const int r   = q & 15;
            const int g   = g0 + gof;
            const int b   = bg * 16 + g;
            const float4 v = *(const float4*)(x + (size_t)b * (Hdim * Wdim)
                                                + (size_t)(py * 16 + r) * Wdim
                                                + px0 * 16 + c4);
            *(float4*)(ss + g * 576 + r * 36 + c4) = v;
        }
    }
    __syncwarp();

    const int g  = g0 + (l >> 4);  // this lane's group (batch)
    const int ln = l & 15;         // row / task index within group
    float2* buf = colbuf[g];
    float* srow = ss + g * 576 + ln * 36;

    float zr[16], zi[16];

    // ---- phase 1: read own row pair from stage, packed row FFT ----
#pragma unroll
    for (int qq = 0; qq < 4; ++qq) {
        float4 va = *(const float4*)(srow + qq * 4);
        float4 vb = *(const float4*)(srow + 16 + qq * 4);
        zr[qq*4+0]=va.x; zr[qq*4+1]=va.y; zr[qq*4+2]=va.z; zr[qq*4+3]=va.w;
        zi[qq*4+0]=vb.x; zi[qq*4+1]=vb.y; zi[qq*4+2]=vb.z; zi[qq*4+3]=vb.w;
    }
    fft16<-1>(zr, zi);

    // Hermitian unpack, store column strips
    buf[0 * 17 + ln]       = make_float2(zr[0], zr[8]);   // A: (X[r,0], X[r,8])
    buf[(8 + 0) * 17 + ln] = make_float2(zi[0], zi[8]);   // B
#pragma unroll
    for (int k = 1; k <= 7; ++k) {
        const int m = 16 - k;
        buf[k * 17 + ln]       = make_float2(0.5f * (zr[k] + zr[m]), 0.5f * (zi[k] - zi[m]));
        buf[(8 + k) * 17 + ln] = make_float2(0.5f * (zi[k] + zi[m]), 0.5f * (zr[m] - zr[k]));
    }
    __syncwarp();

    // ---- phase 2: column task (tile = ln>>3, tt = ln&7) ----
    {
        const int tile = ln >> 3;
        const int tt   = ln & 7;
        float2* strip = buf + ln * 17;
#pragma unroll
        for (int r = 0; r < 16; ++r) { float2 v = strip[r]; zr[r] = v.x; zi[r] = v.y; }

        fft16<-1>(zr, zi);

        const float* Sp = sS[tile];
        if (tt == 0) {
            // packed real cols 0 & 8 (S_sym even in ky at kx=0,8)
#pragma unroll
            for (int ky = 0; ky <= 8; ++ky) {
                const int m = (16 - ky) & 15;
                const float s0 = Sp[ky * 16 + 0];
                const float s8 = Sp[ky * 16 + 8];
                const float c0r = 0.5f * (zr[ky] + zr[m]);
                const float c0i = 0.5f * (zi[ky] - zi[m]);
                const float c8r = 0.5f * (zi[ky] + zi[m]);
                const float c8i = 0.5f * (zr[m] - zr[ky]);
                const float ar = c0r * s0, ai = c0i * s0;
                const float br = c8r * s8, bi = c8i * s8;
                zr[ky] = ar - bi;  zi[ky] = ai + br;
                if (m != ky) { zr[m] = ar + bi; zi[m] = br - ai; }
            }
        } else {
#pragma unroll
            for (int ky = 0; ky < 16; ++ky) {
                const float s = Sp[ky * 16 + tt];
                zr[ky] *= s;  zi[ky] *= s;
            }
        }

        fft16<1>(zr, zi);

#pragma unroll
        for (int i = 0; i < 16; ++i) strip[i] = make_float2(zr[i], zi[i]);
    }
    __syncwarp();

    // ---- phase 3: Hermitian-extend W rows, packed inverse row FFT ----
    {
        float2 a0 = buf[0 * 17 + ln];
        float2 b0 = buf[(8 + 0) * 17 + ln];
        zr[0] = a0.x;  zi[0] = b0.x;
        zr[8] = a0.y;  zi[8] = b0.y;
#pragma unroll
        for (int k = 1; k <= 7; ++k) {
            float2 a = buf[k * 17 + ln];        // W_A[i,k]
            float2 c = buf[(8 + k) * 17 + ln];  // W_B[i,k]
            zr[k]      = a.x - c.y;   zi[k]      = a.y + c.x;   // W_A + i W_B
            zr[16 - k] = a.x + c.y;   zi[16 - k] = c.x - a.y;   // conj ext
        }
    }
    fft16<1>(zr, zi);

    // ---- epilogue: +bias into stage rows (overwrites strips; same warp) ----
    {
        const float* bA = sBt[0];
        const float* bB = sBt[1];
#pragma unroll
        for (int j = 0; j < 16; j += 4) {
            float4 oa, ob;
            oa.x = zr[j+0] + bA[(j+0)*16 + ln];
            oa.y = zr[j+1] + bA[(j+1)*16 + ln];
            oa.z = zr[j+2] + bA[(j+2)*16 + ln];
            oa.w = zr[j+3] + bA[(j+3)*16 + ln];
            ob.x = zi[j+0] + bB[(j+0)*16 + ln];
            ob.y = zi[j+1] + bB[(j+1)*16 + ln];
            ob.z = zi[j+2] + bB[(j+2)*16 + ln];
            ob.w = zi[j+3] + bB[(j+3)*16 + ln];
            *(float4*)(srow + j)      = oa;
            *(float4*)(srow + 16 + j) = ob;
        }
    }
    __syncwarp();

    // ---- staged coalesced store: 8 x STG.128, full sectors ----
    {
        const int seg = l >> 3;
        const int c4  = (l & 7) * 4;
#pragma unroll
        for (int i = 0; i < 8; ++i) {
            const int q   = i * 4 + seg;
            const int gof = q >> 4;
            const int r   = q & 15;
            const int gg  = g0 + gof;
            const int b   = bg * 16 + gg;
            float4 v = *(const float4*)(ss + gg * 576 + r * 36 + c4);
            *(float4*)(y + (size_t)b * (Hdim * Wdim)
                         + (size_t)(py * 16 + r) * Wdim
                         + px0 * 16 + c4) = v;
        }
    }
}

extern "C" void kernel_launch(void* const* d_in, const int* in_sizes, int n_in,
                              void* d_out, int out_size)
{
    const float* x      = (const float*)d_in[0];
    const float* logits = (const float*)d_in[1];
    const float* mu     = (const float*)d_in[2];
    const float* sigma  = (const float*)d_in[3];
    const float* bias   = (const float*)d_in[4];
    float* y = (float*)d_out;

    make_S_kernel<<<Pn, 256>>>(logits, mu, sigma);
    patch_spectral_kernel<<<2048, 256>>>(x, bias, y);
}

// round 6
// speedup vs baseline: 1.8065x; 1.0068x over previous
#include <cuda_runtime.h>
#include <cuda_bf16.h>

#define Hdim 512
#define Wdim 512
#define Qn 3
#define Pn 1024
#define Bn 64
#define JITTER 1e-6f

// Precomputed symmetrized spectrum: S_sym[p][ky*16+kx] / 256
__device__ float g_S[Pn * 256];

// ---------------------------------------------------------------------------
// Kernel A: build S per patch (separable Gaussians), then index-symmetrize:
//   S_sym[k] = (S[k] + S[(-k) mod 16]) / 2    (makes Xf*S exactly Hermitian)
// ---------------------------------------------------------------------------
__global__ __launch_bounds__(256) void make_S_kernel(
    const float* __restrict__ logits,
    const float* __restrict__ mu,
    const float* __restrict__ sigma)
{
    __shared__ float w[4];
    __shared__ float gy[6][16];
    __shared__ float gx[6][16];
    __shared__ float sAcc[256];

    const int p = blockIdx.x;
    const int t = threadIdx.x;

    if (t == 0) {
        const float l0 = logits[p * Qn + 0];
        const float l1 = logits[p * Qn + 1];
        const float l2 = logits[p * Qn + 2];
        const float mx = fmaxf(l0, fmaxf(l1, l2));
        const float e0 = expf(l0 - mx);
        const float e1 = expf(l1 - mx);
        const float e2 = expf(l2 - mx);
        const float inv = 1.0f / (e0 + e1 + e2);
        w[0] = e0 * inv; w[1] = e1 * inv; w[2] = e2 * inv;
    }
    if (t < 192) {
        const int axis = t / 96;
        const int rem  = t % 96;
        const int qs   = rem >> 4;
        const int k    = rem & 15;
        const int q    = qs >> 1;
        const int sgn  = qs & 1;
        const float f  = (float)(k < 8 ? k : k - 16) * (1.0f / 16.0f);
        const int base = (p * Qn + q) * 2;
        const float m  = mu[base + axis];
        const float s  = sigma[base + axis];
        const float d  = (sgn ? (f + m) : (f - m)) / s;
        const float v  = expf(-0.5f * d * d);
        if (axis == 0) gy[qs][k] = v; else gx[qs][k] = v;
    }
    __syncthreads();

    const int ky = t >> 4;
    const int kx = t & 15;
    float acc = 0.0f;
#pragma unroll
    for (int q = 0; q < Qn; ++q) {
        acc += w[q] * (gy[2 * q][ky] * gx[2 * q][kx] +
                       gy[2 * q + 1][ky] * gx[2 * q + 1][kx]);
    }
    sAcc[t] = acc;
    __syncthreads();

    const int tm = (((16 - ky) & 15) << 4) | ((16 - kx) & 15);
    const float ssym = 0.5f * (sAcc[t] + sAcc[tm]) + JITTER;
    g_S[p * 256 + t] = ssym * (1.0f / 256.0f);
}

// ---------------------------------------------------------------------------
// Fully unrolled 16-point complex FFT. DIR=-1 fwd, DIR=+1 inv (unnormalized).
// ---------------------------------------------------------------------------
template<int DIR>
__device__ __forceinline__ void fft16(float re[16], float im[16]) {
#define SWAPF(a,b) { float _t=re[a]; re[a]=re[b]; re[b]=_t; _t=im[a]; im[a]=im[b]; im[b]=_t; }
    SWAPF(1, 8) SWAPF(2, 4) SWAPF(3, 12) SWAPF(5, 10) SWAPF(7, 14) SWAPF(11, 13)
#undef SWAPF
    const float CT[8] = { 1.0f,  0.9238795325112867f,  0.7071067811865476f,  0.3826834323650898f,
                          0.0f, -0.3826834323650898f, -0.7071067811865476f, -0.9238795325112867f };
    const float ST[8] = { 0.0f,  0.3826834323650898f,  0.7071067811865476f,  0.9238795325112867f,
                          1.0f,  0.9238795325112867f,  0.7071067811865476f,  0.3826834323650898f };
#pragma unroll
    for (int s = 1; s <= 4; ++s) {
        const int len   = 1 << s;
        const int half  = len >> 1;
        const int tstep = 16 >> s;
#pragma unroll
        for (int i = 0; i < 16; i += len) {
#pragma unroll
            for (int j = 0; j < half; ++j) {
                const float c  = CT[j * tstep];
                const float sn = (float)DIR * ST[j * tstep];
                const int a = i + j;
                const int b = a + half;
                float br = re[b], bi = im[b];
                float tr = c * br - sn * bi;
                float ti = c * bi + sn * br;
                re[b] = re[a] - tr;
                im[b] = im[a] - ti;
                re[a] += tr;
                im[a] += ti;
            }
        }
    }
}

// ---------------------------------------------------------------------------
// Kernel B: block = one adjacent patch pair (A,B) x 16 batches.
// Identical to round 5 except the register budget: launch_bounds(256,3)
// gives 85 regs (was 64) to eliminate local-memory spills.
// ---------------------------------------------------------------------------
__global__ __launch_bounds__(256, 3) void patch_spectral_kernel(
    const float* __restrict__ x,
    const float* __restrict__ bias,
    float* __restrict__ y)
{
    __shared__ float2 colbuf[16][288];   // per group: stage (576 f) / strips (272 f2)
    __shared__ float  sS[2][272];        // S_sym/256 per patch of the pair
    __shared__ float  sBt[2][272];       // bias transposed: sBt[h][j*16+i]

    const int pp = blockIdx.x & 511;     // patch-pair index
    const int bg = blockIdx.x >> 9;      // batch group (16 batches)
    const int t  = threadIdx.x;
    const int p0 = pp * 2;

#pragma unroll
    for (int hh = 0; hh < 2; ++hh) {
        sS[hh][t] = g_S[(p0 + hh) * 256 + t];
        sBt[hh][(t & 15) * 16 + (t >> 4)] = bias[(p0 + hh) * 256 + t];
    }
    __syncthreads();

    const int wrp = t >> 5;       // warp 0..7
    const int l   = t & 31;       // lane
    const int g0  = wrp * 2;      // two groups (batches) per warp
    const int py  = p0 >> 5;
    const int px0 = p0 & 31;

    float* ss = (float*)colbuf;   // flat stage view

    // ---- staged coalesced load: 8 x LDG.128, each instr = 4 full segments --
    {
        const int seg = l >> 3;          // which of 4 segments this lane serves
        const int c4  = (l & 7) * 4;     // float offset within 128B segment
#pragma unroll
        for (int i = 0; i < 8; ++i) {
            const int q   = i * 4 + seg;        // 0..31
            const int gof = q >> 4;
            const int r   = q & 15;
            const int g   = g0 + gof;
            const int b   = bg * 16 + g;
            const float4 v = *(const float4*)(x + (size_t)b * (Hdim * Wdim)
                                                + (size_t)(py * 16 + r) * Wdim
                                                + px0 * 16 + c4);
            *(float4*)(ss + g * 576 + r * 36 + c4) = v;
        }
    }
    __syncwarp();

    const int g  = g0 + (l >> 4);  // this lane's group (batch)
    const int ln = l & 15;         // row / task index within group
    float2* buf = colbuf[g];
    float* srow = ss + g * 576 + ln * 36;

    float zr[16], zi[16];

    // ---- phase 1: read own row pair from stage, packed row FFT ----
#pragma unroll
    for (int qq = 0; qq < 4; ++qq) {
        float4 va = *(const float4*)(srow + qq * 4);
        float4 vb = *(const float4*)(srow + 16 + qq * 4);
        zr[qq*4+0]=va.x; zr[qq*4+1]=va.y; zr[qq*4+2]=va.z; zr[qq*4+3]=va.w;
        zi[qq*4+0]=vb.x; zi[qq*4+1]=vb.y; zi[qq*4+2]=vb.z; zi[qq*4+3]=vb.w;
    }
    fft16<-1>(zr, zi);

    // Hermitian unpack, store column strips
    buf[0 * 17 + ln]       = make_float2(zr[0], zr[8]);   // A: (X[r,0], X[r,8])
    buf[(8 + 0) * 17 + ln] = make_float2(zi[0], zi[8]);   // B
#pragma unroll
    for (int k = 1; k <= 7; ++k) {
        const int m = 16 - k;
        buf[k * 17 + ln]       = make_float2(0.5f * (zr[k] + zr[m]), 0.5f * (zi[k] - zi[m]));
        buf[(8 + k) * 17 + ln] = make_float2(0.5f * (zi[k] + zi[m]), 0.5f * (zr[m] - zr[k]));
    }
    __syncwarp();

    // ---- phase 2: column task (tile = ln>>3, tt = ln&7) ----
    {
        const int tile = ln >> 3;
        const int tt   = ln & 7;
        float2* strip = buf + ln * 17;
#pragma unroll
        for (int r = 0; r < 16; ++r) { float2 v = strip[r]; zr[r] = v.x; zi[r] = v.y; }

        fft16<-1>(zr, zi);

        const float* Sp = sS[tile];
        if (tt == 0) {
            // packed real cols 0 & 8 (S_sym even in ky at kx=0,8)
#pragma unroll
            for (int ky = 0; ky <= 8; ++ky) {
                const int m = (16 - ky) & 15;
                const float s0 = Sp[ky * 16 + 0];
                const float s8 = Sp[ky * 16 + 8];
                const float c0r = 0.5f * (zr[ky] + zr[m]);
                const float c0i = 0.5f * (zi[ky] - zi[m]);
                const float c8r = 0.5f * (zi[ky] + zi[m]);
                const float c8i = 0.5f * (zr[m] - zr[ky]);
                const float ar = c0r * s0, ai = c0i * s0;
                const float br = c8r * s8, bi = c8i * s8;
                zr[ky] = ar - bi;  zi[ky] = ai + br;
                if (m != ky) { zr[m] = ar + bi; zi[m] = br - ai; }
            }
        } else {
#pragma unroll
            for (int ky = 0; ky < 16; ++ky) {
                const float s = Sp[ky * 16 + tt];
                zr[ky] *= s;  zi[ky] *= s;
            }
        }

        fft16<1>(zr, zi);

#pragma unroll
        for (int i = 0; i < 16; ++i) strip[i] = make_float2(zr[i], zi[i]);
    }
    __syncwarp();

    // ---- phase 3: Hermitian-extend W rows, packed inverse row FFT ----
    {
        float2 a0 = buf[0 * 17 + ln];
        float2 b0 = buf[(8 + 0) * 17 + ln];
        zr[0] = a0.x;  zi[0] = b0.x;
        zr[8] = a0.y;  zi[8] = b0.y;
#pragma unroll
        for (int k = 1; k <= 7; ++k) {
            float2 a = buf[k * 17 + ln];        // W_A[i,k]
            float2 c = buf[(8 + k) * 17 + ln];  // W_B[i,k]
            zr[k]      = a.x - c.y;   zi[k]      = a.y + c.x;   // W_A + i W_B
            zr[16 - k] = a.x + c.y;   zi[16 - k] = c.x - a.y;   // conj ext
        }
    }
    fft16<1>(zr, zi);

    // ---- epilogue: +bias into stage rows (overwrites strips; same warp) ----
    {
        const float* bA = sBt[0];
        const float* bB = sBt[1];
#pragma unroll
        for (int j = 0; j < 16; j += 4) {
            float4 oa, ob;
            oa.x = zr[j+0] + bA[(j+0)*16 + ln];
            oa.y = zr[j+1] + bA[(j+1)*16 + ln];
            oa.z = zr[j+2] + bA[(j+2)*16 + ln];
            oa.w = zr[j+3] + bA[(j+3)*16 + ln];
            ob.x = zi[j+0] + bB[(j+0)*16 + ln];
            ob.y = zi[j+1] + bB[(j+1)*16 + ln];
            ob.z = zi[j+2] + bB[(j+2)*16 + ln];
            ob.w = zi[j+3] + bB[(j+3)*16 + ln];
            *(float4*)(srow + j)      = oa;
            *(float4*)(srow + 16 + j) = ob;
        }
    }
    __syncwarp();

    // ---- staged coalesced store: 8 x STG.128, full sectors ----
    {
        const int seg = l >> 3;
        const int c4  = (l & 7) * 4;
#pragma unroll
        for (int i = 0; i < 8; ++i) {
            const int q   = i * 4 + seg;
            const int gof = q >> 4;
            const int r   = q & 15;
            const int gg  = g0 + gof;
            const int b   = bg * 16 + gg;
            float4 v = *(const float4*)(ss + gg * 576 + r * 36 + c4);
            *(float4*)(y + (size_t)b * (Hdim * Wdim)
                         + (size_t)(py * 16 + r) * Wdim
                         + px0 * 16 + c4) = v;
        }
    }
}

extern "C" void kernel_launch(void* const* d_in, const int* in_sizes, int n_in,
                              void* d_out, int out_size)
{
    const float* x      = (const float*)d_in[0];
    const float* logits = (const float*)d_in[1];
    const float* mu     = (const float*)d_in[2];
    const float* sigma  = (const float*)d_in[3];
    const float* bias   = (const float*)d_in[4];
    float* y = (float*)d_out;

    make_S_kernel<<<Pn, 256>>>(logits, mu, sigma);
    patch_spectral_kernel<<<2048, 256>>>(x, bias, y);
}